// round 4
// baseline (speedup 1.0000x reference)
#include <cuda_runtime.h>

// CFConv: y[i] = sum_{e: idx_i[e]==i} x[idx_j[e]] * Wij[e]
// x:[50000,64] f32, Wij:[E=1.25M,64] f32, idx_i sorted.
//
// R4: half-warp float4 layout (R3) + explicit 3-stage software pipeline:
//   W stream prefetched depth-3 (DRAM latency), x gather depth-2 (L2 latency),
//   idx depth-2 (L1). Sorted-segment register accumulation; interior segments
//   flushed with plain stores (exclusive ownership), boundary segments with
//   red.global.add.v4.f32.

#define FEAT   64
#define F4     (FEAT / 4)      // 16 float4 per row
#define HALF   128             // edges per half-warp
#define CHUNK  (2 * HALF)      // edges per warp
#define MAX_E  1250000

__device__ int2 g_idx[MAX_E];

__global__ __launch_bounds__(256) void pack_idx_kernel(
    const void* __restrict__ ii_p, const void* __restrict__ jj_p, int E)
{
    int e = blockIdx.x * blockDim.x + threadIdx.x;
    if (e >= E) return;
    // dtype probe: LE int64 -> int32 word at odd position (E/2)|1 is a zero
    // high word; int32 -> sorted idx_i median ~N/2 != 0.
    int probe = reinterpret_cast<const int*>(ii_p)[(E / 2) | 1];
    int a, b;
    if (probe == 0) {
        a = (int)reinterpret_cast<const long long*>(ii_p)[e];
        b = (int)reinterpret_cast<const long long*>(jj_p)[e];
    } else {
        a = reinterpret_cast<const int*>(ii_p)[e];
        b = reinterpret_cast<const int*>(jj_p)[e];
    }
    g_idx[e] = make_int2(a, b);
}

__device__ __forceinline__ void red_add_f4(float* p, float4 v) {
    asm volatile("red.global.add.v4.f32 [%0], {%1,%2,%3,%4};"
                 :: "l"(p), "f"(v.x), "f"(v.y), "f"(v.z), "f"(v.w)
                 : "memory");
}

__device__ __forceinline__ void fma4(float4& a, float4 x, float4 w) {
    a.x = fmaf(x.x, w.x, a.x);
    a.y = fmaf(x.y, w.y, a.y);
    a.z = fmaf(x.z, w.z, a.z);
    a.w = fmaf(x.w, w.w, a.w);
}

__device__ __forceinline__ void flush(float* __restrict__ y, int seg, int fl,
                                      float4 acc, bool& first)
{
    float* dst = y + (size_t)seg * FEAT + fl * 4;
    if (first) { red_add_f4(dst, acc); first = false; }
    else       { *reinterpret_cast<float4*>(dst) = acc; }  // exclusive interior
}

__global__ __launch_bounds__(256) void cfconv_kernel(
    const float4* __restrict__ X4, const float4* __restrict__ W4,
    float* __restrict__ y, int E)
{
    int gwarp = (blockIdx.x * blockDim.x + threadIdx.x) >> 5;
    int lane  = threadIdx.x & 31;
    int half  = lane >> 4;
    int fl    = lane & 15;

    long long base = (long long)gwarp * CHUNK;
    if (base >= E) return;

    long long s  = base + (long long)half * HALF;
    if (s >= E) return;
    long long se = s + HALF;
    if (se > E) se = E;
    int cnt = (int)(se - s);

    const int2*   ip = g_idx + s;
    const float4* wp = W4 + (size_t)s * F4 + fl;

    int    prev;
    bool   first = true;     // first segment may start before s -> atomic
    float4 acc   = make_float4(0.f, 0.f, 0.f, 0.f);

    if (cnt == HALF) {
        // ---------- pipelined full-chunk path ----------
        int2   idA = ip[0];
        int2   idB = ip[1];
        float4 wA  = __ldcs(wp);
        float4 wB  = __ldcs(wp + F4);
        float4 wC  = __ldcs(wp + 2 * F4);
        float4 xA  = X4[(size_t)idA.y * F4 + fl];
        float4 xB  = X4[(size_t)idB.y * F4 + fl];
        prev = idA.x;

        #pragma unroll 2
        for (int k = 2; k < HALF; ++k) {
            // stage-in: idx/x depth-2, W depth-3 (clamped in-bounds)
            int2   idN = ip[k];
            float4 xN  = X4[(size_t)idN.y * F4 + fl];
            long long kp = (s + k + 1 < (long long)E) ? (k + 1) : k;
            float4 wN  = __ldcs(wp + (size_t)kp * F4);

            // consume stage A
            if (idA.x != prev) {
                flush(y, prev, fl, acc, first);
                acc  = make_float4(0.f, 0.f, 0.f, 0.f);
                prev = idA.x;
            }
            fma4(acc, xA, wA);

            // rotate
            idA = idB; xA = xB; wA = wB;
            idB = idN; xB = xN; wB = wC; wC = wN;
        }
        // epilogue: A then B
        if (idA.x != prev) {
            flush(y, prev, fl, acc, first);
            acc = make_float4(0.f, 0.f, 0.f, 0.f);
            prev = idA.x;
        }
        fma4(acc, xA, wA);
        if (idB.x != prev) {
            flush(y, prev, fl, acc, first);
            acc = make_float4(0.f, 0.f, 0.f, 0.f);
            prev = idB.x;
        }
        fma4(acc, xB, wB);
    } else {
        // ---------- scalar tail path (at most one partial sub-chunk) ----------
        int2   idc = ip[0];
        float4 wc  = __ldcs(wp);
        float4 xc  = X4[(size_t)idc.y * F4 + fl];
        prev = idc.x;

        for (int k = 1; k < cnt; ++k) {
            int2   idn = ip[k];
            float4 wn  = __ldcs(wp + (size_t)k * F4);
            float4 xn  = X4[(size_t)idn.y * F4 + fl];
            if (idc.x != prev) {
                flush(y, prev, fl, acc, first);
                acc  = make_float4(0.f, 0.f, 0.f, 0.f);
                prev = idc.x;
            }
            fma4(acc, xc, wc);
            idc = idn; wc = wn; xc = xn;
        }
        if (idc.x != prev) {
            flush(y, prev, fl, acc, first);
            acc  = make_float4(0.f, 0.f, 0.f, 0.f);
            prev = idc.x;
        }
        fma4(acc, xc, wc);
    }

    // final segment may extend into the next sub-chunk -> atomic
    red_add_f4(y + (size_t)prev * FEAT + fl * 4, acc);
}

extern "C" void kernel_launch(void* const* d_in, const int* in_sizes, int n_in,
                              void* d_out, int out_size)
{
    const float* x   = (const float*)d_in[0];   // [N, 64]
    const float* Wij = (const float*)d_in[1];   // [E, 64]
    const void*  ii  = d_in[2];                 // [E] int64 or int32
    const void*  jj  = d_in[3];                 // [E] int64 or int32
    float*       y   = (float*)d_out;           // [N, 64]

    int E = in_sizes[1] / FEAT;

    cudaMemsetAsync(d_out, 0, (size_t)out_size * sizeof(float), 0);
    pack_idx_kernel<<<(E + 255) / 256, 256>>>(ii, jj, E);

    int nwarps  = (E + CHUNK - 1) / CHUNK;
    int nblocks = (nwarps + 7) / 8;             // 8 warps / 256-thread block
    cfconv_kernel<<<nblocks, 256>>>((const float4*)x, (const float4*)Wij, y, E);
}

// round 5
// speedup vs baseline: 1.5780x; 1.5780x over previous
#include <cuda_runtime.h>

// CFConv: y[i] = sum_{e: idx_i[e]==i} x[idx_j[e]] * Wij[e]
// x:[50000,64] f32, Wij:[E=1.25M,64] f32, idx_i sorted.
//
// R5: identical inner loop to R3 (depth-1 pipeline, half-warp float4 lanes,
// sorted-segment register accumulation, plain stores for interior segments,
// red.global.add.v4.f32 at task boundaries). Only change: HALF 128 -> 64,
// doubling the number of blocks (611 -> 1221) so occupancy reaches the
// 5-block/SM cap instead of being grid-limited at 4.13 blocks/SM.

#define FEAT   64
#define F4     (FEAT / 4)      // 16 float4 per row
#define HALF   64              // edges per half-warp task
#define CHUNK  (2 * HALF)      // edges per warp
#define MAX_E  1250000

__device__ int2 g_idx[MAX_E];

// Pack idx_i/idx_j (int64 or int32, runtime-probed) into int2 {i, j}.
__global__ __launch_bounds__(256) void pack_idx_kernel(
    const void* __restrict__ ii_p, const void* __restrict__ jj_p, int E)
{
    int e = blockIdx.x * blockDim.x + threadIdx.x;
    if (e >= E) return;
    // LE int64 data: int32 word at odd position (E/2)|1 is a high word == 0.
    // int32 data: sorted idx_i median ~N/2 != 0.
    int probe = reinterpret_cast<const int*>(ii_p)[(E / 2) | 1];
    int a, b;
    if (probe == 0) {
        a = (int)reinterpret_cast<const long long*>(ii_p)[e];
        b = (int)reinterpret_cast<const long long*>(jj_p)[e];
    } else {
        a = reinterpret_cast<const int*>(ii_p)[e];
        b = reinterpret_cast<const int*>(jj_p)[e];
    }
    g_idx[e] = make_int2(a, b);
}

__device__ __forceinline__ void red_add_f4(float* p, float4 v) {
    asm volatile("red.global.add.v4.f32 [%0], {%1,%2,%3,%4};"
                 :: "l"(p), "f"(v.x), "f"(v.y), "f"(v.z), "f"(v.w)
                 : "memory");
}

__global__ __launch_bounds__(256, 5) void cfconv_kernel(
    const float4* __restrict__ X4, const float4* __restrict__ W4,
    float* __restrict__ y, int E)
{
    int gwarp = (blockIdx.x * blockDim.x + threadIdx.x) >> 5;
    int lane  = threadIdx.x & 31;
    int half  = lane >> 4;         // which half-warp
    int fl    = lane & 15;         // float4 slot within the feature row

    long long base = (long long)gwarp * CHUNK;
    if (base >= E) return;

    long long s  = base + (long long)half * HALF;
    long long se = s + HALF;
    if (se > E) se = E;
    int cnt = (s < E) ? (int)(se - s) : 0;   // edges this half processes
    if (cnt <= 0) return;                    // inactive half (tail chunk)

    const int2*   ip = g_idx + s;
    const float4* wp = W4 + (size_t)s * F4 + fl;

    // primer: edge 0
    int2   idc = ip[0];
    float4 wc  = __ldcs(wp);
    float4 xc  = X4[(size_t)idc.y * F4 + fl];

    int    prev  = idc.x;
    bool   first = true;           // first segment may start before s -> atomic
    float4 acc   = make_float4(0.f, 0.f, 0.f, 0.f);

    for (int k = 1; k < cnt; ++k) {
        // issue next-iteration loads before consuming current (depth-1 pipeline)
        int2   idn = ip[k];
        float4 wn  = __ldcs(wp + (size_t)k * F4);
        float4 xn  = X4[(size_t)idn.y * F4 + fl];

        // process current edge
        if (idc.x != prev) {
            float* dst = y + (size_t)prev * FEAT + fl * 4;
            if (first) { red_add_f4(dst, acc); first = false; }
            else       { *reinterpret_cast<float4*>(dst) = acc; }  // exclusive interior segment
            acc  = make_float4(0.f, 0.f, 0.f, 0.f);
            prev = idc.x;
        }
        acc.x = fmaf(xc.x, wc.x, acc.x);
        acc.y = fmaf(xc.y, wc.y, acc.y);
        acc.z = fmaf(xc.z, wc.z, acc.z);
        acc.w = fmaf(xc.w, wc.w, acc.w);

        idc = idn; wc = wn; xc = xn;
    }

    // last edge
    if (idc.x != prev) {
        float* dst = y + (size_t)prev * FEAT + fl * 4;
        if (first) { red_add_f4(dst, acc); first = false; }
        else       { *reinterpret_cast<float4*>(dst) = acc; }
        acc  = make_float4(0.f, 0.f, 0.f, 0.f);
        prev = idc.x;
    }
    acc.x = fmaf(xc.x, wc.x, acc.x);
    acc.y = fmaf(xc.y, wc.y, acc.y);
    acc.z = fmaf(xc.z, wc.z, acc.z);
    acc.w = fmaf(xc.w, wc.w, acc.w);

    // final segment may extend into the next sub-chunk -> atomic
    red_add_f4(y + (size_t)prev * FEAT + fl * 4, acc);
}

extern "C" void kernel_launch(void* const* d_in, const int* in_sizes, int n_in,
                              void* d_out, int out_size)
{
    const float* x   = (const float*)d_in[0];   // [N, 64]
    const float* Wij = (const float*)d_in[1];   // [E, 64]
    const void*  ii  = d_in[2];                 // [E] int64 or int32
    const void*  jj  = d_in[3];                 // [E] int64 or int32
    float*       y   = (float*)d_out;           // [N, 64]

    int E = in_sizes[1] / FEAT;

    // zero output (memset node — graph-capturable)
    cudaMemsetAsync(d_out, 0, (size_t)out_size * sizeof(float), 0);

    // pack indices into int2 scratch
    pack_idx_kernel<<<(E + 255) / 256, 256>>>(ii, jj, E);

    // main segmented gather-multiply-scatter
    int nwarps  = (E + CHUNK - 1) / CHUNK;
    int nblocks = (nwarps + 7) / 8;             // 8 warps / 256-thread block
    cfconv_kernel<<<nblocks, 256>>>((const float4*)x, (const float4*)Wij, y, E);
}